// round 15
// baseline (speedup 1.0000x reference)
#include <cuda_runtime.h>
#include <math.h>

#define TB   8
#define TBC  4        // batch rows per chain
#define TD   512
#define TDD  1024
#define TT   4096
#define NCTA 128
#define CJ   8        // h cols per CTA
#define CI   4        // p cols per CTA
#define NTHR 256
#define NWARP 8

__device__ float gMem[TB * TD];    // rows 0-3 chain A, 4-7 chain B
__device__ float gH[TB * TDD];
__device__ __align__(256) unsigned gBarHA[64];
__device__ __align__(256) unsigned gBarHB[64];
__device__ __align__(256) unsigned gBarMA[64];
__device__ __align__(256) unsigned gBarMB[64];

__global__ void init_scratch() {
    int t = blockIdx.x * blockDim.x + threadIdx.x;
    if (t < TB * TD) gMem[t] = 0.0f;
    if (t < 64) { gBarHA[t] = 0u; gBarHB[t] = 0u; gBarMA[t] = 0u; gBarMB[t] = 0u; }
}

__device__ __forceinline__ void fma2(unsigned long long& acc,
                                     unsigned long long a,
                                     unsigned long long b) {
    asm volatile("fma.rn.f32x2 %0, %1, %2, %0;" : "+l"(acc) : "l"(a), "l"(b));
}
__device__ __forceinline__ float2 u2f(unsigned long long v) {
    float2 f;
    asm("mov.b64 {%0,%1}, %2;" : "=f"(f.x), "=f"(f.y) : "l"(v));
    return f;
}
__device__ __forceinline__ ulonglong2 ldg128_cg(const void* p) {
    ulonglong2 v;
    asm volatile("ld.global.cg.v2.u64 {%0,%1}, [%2];"
                 : "=l"(v.x), "=l"(v.y) : "l"(p));
    return v;
}
__device__ __forceinline__ ulonglong2 ldg128_nc(const void* p) {
    ulonglong2 v;
    asm volatile("ld.global.nc.v2.u64 {%0,%1}, [%2];"
                 : "=l"(v.x), "=l"(v.y) : "l"(p));
    return v;
}
__device__ __forceinline__ void stg_cg(float* p, float v) {
    asm volatile("st.global.cg.f32 [%0], %1;" :: "l"(p), "f"(v) : "memory");
}
__device__ __forceinline__ void bar_arrive(unsigned* ctr) {
    unsigned one = 1u;
    asm volatile("red.release.gpu.global.add.u32 [%0], %1;"
                 :: "l"(ctr), "r"(one) : "memory");
}
__device__ __forceinline__ void bar_spin(const unsigned* ctr, unsigned tgt) {
    unsigned v;
    do {
        asm volatile("ld.relaxed.gpu.global.u32 %0, [%1];"
                     : "=r"(v) : "l"(ctr) : "memory");
    } while (v < tgt);
}

__global__ void __launch_bounds__(NTHR, 1)
sys2_kernel(const float* __restrict__ x,
            const float* __restrict__ W1,
            const float* __restrict__ b1,
            const float* __restrict__ W2,
            const float* __restrict__ b2,
            float* __restrict__ y)
{
    extern __shared__ float smem[];
    float* sW1   = smem;                     // CJ*TDD (32 KB)
    float* sW2   = sW1 + CJ * TDD;           // CI*TDD (16 KB)
    float* sP1   = sW2 + CI * TDD;           // NWARP*32 (G1 partials)
    float* sP2   = sP1 + NWARP * 32;         // NWARP*16 (G2 partials)
    float* sB1   = sP2 + NWARP * 16;         // CJ
    float* sB2   = sB1 + CJ;                 // CI

    const int cta  = blockIdx.x;
    const int tid  = threadIdx.x;
    const int w    = tid >> 5;
    const int lane = tid & 31;
    const int b4   = lane >> 3;   // 0..3 (row within chain)
    const int kq   = lane & 7;    // k-phase (8 per warp)
    const int jbase = cta * CJ;
    const int ibase = cta * CI;
    const int k1 = (w << 6) + (kq << 3);   // GEMM1: lane covers 8 k
    const int k2 = (w << 7) + (kq << 4);   // GEMM2: lane covers 16 k

    {
        const float4* g1 = (const float4*)(W1 + (size_t)jbase * TDD);
        float4* s1 = (float4*)sW1;
        for (int idx = tid; idx < CJ * TDD / 4; idx += NTHR) s1[idx] = g1[idx];
        const float4* g2 = (const float4*)(W2 + (size_t)ibase * TDD);
        float4* s2 = (float4*)sW2;
        for (int idx = tid; idx < CI * TDD / 4; idx += NTHR) s2[idx] = g2[idx];
        if (tid < CJ) sB1[tid] = b1[jbase + tid];
        if (tid < CI) sB2[tid] = b2[ibase + tid];
    }
    __syncthreads();

    float memA = 0.0f, memB = 0.0f;   // tid<16 owns (bb=tid>>2, ii=tid&3)

    // preload x(0) for both chains
    ulonglong2 exA[2], exB[2];
    exA[0] = ldg128_nc(x + ((size_t)b4 * TT) * TD + k1);
    exA[1] = ldg128_nc(x + ((size_t)b4 * TT) * TD + k1 + 4);
    exB[0] = ldg128_nc(x + ((size_t)(b4 + TBC) * TT) * TD + k1);
    exB[1] = ldg128_nc(x + ((size_t)(b4 + TBC) * TT) * TD + k1 + 4);

    for (int t = 0; t < TT; ++t) {
        // ================= Phase 1: G1A — h rows 0-3 =================
        {
            unsigned long long ax[CJ], ay[CJ];
#pragma unroll
            for (int j = 0; j < CJ; ++j) { ax[j] = 0ull; ay[j] = 0ull; }
            // x-half (independent) before the wait
#pragma unroll
            for (int j = 0; j < CJ; ++j) {
                const ulonglong2 w0 = *(const ulonglong2*)(sW1 + j * TDD + k1);
                const ulonglong2 w1 = *(const ulonglong2*)(sW1 + j * TDD + k1 + 4);
                fma2(ax[j], w0.x, exA[0].x); fma2(ay[j], w0.y, exA[0].y);
                fma2(ax[j], w1.x, exA[1].x); fma2(ay[j], w1.y, exA[1].y);
            }
            if (t > 0 && tid == 0) bar_spin(&gBarMA[0], (unsigned)t * NCTA);
            __syncthreads();
            const ulonglong2 em0 = ldg128_cg(gMem + b4 * TD + k1);
            const ulonglong2 em1 = ldg128_cg(gMem + b4 * TD + k1 + 4);
#pragma unroll
            for (int j = 0; j < CJ; ++j) {
                const ulonglong2 w0 = *(const ulonglong2*)(sW1 + j * TDD + TD + k1);
                const ulonglong2 w1 = *(const ulonglong2*)(sW1 + j * TDD + TD + k1 + 4);
                fma2(ax[j], w0.x, em0.x); fma2(ay[j], w0.y, em0.y);
                fma2(ax[j], w1.x, em1.x); fma2(ay[j], w1.y, em1.y);
            }
#pragma unroll
            for (int j = 0; j < CJ; ++j) {
                const float2 fx = u2f(ax[j]);
                const float2 fy = u2f(ay[j]);
                float s = (fx.x + fx.y) + (fy.x + fy.y);
                s += __shfl_xor_sync(0xffffffffu, s, 1);
                s += __shfl_xor_sync(0xffffffffu, s, 2);
                s += __shfl_xor_sync(0xffffffffu, s, 4);
                if (kq == 0) sP1[(w << 5) + (b4 << 3) + j] = s;
            }
            __syncthreads();
            if (tid < TBC * CJ) {   // 32 threads (warp 0)
                const int bb = tid >> 3, jj = tid & 7;
                const float s0 = sP1[0 * 32 + tid] + sP1[1 * 32 + tid];
                const float s1 = sP1[2 * 32 + tid] + sP1[3 * 32 + tid];
                const float s2 = sP1[4 * 32 + tid] + sP1[5 * 32 + tid];
                const float s3 = sP1[6 * 32 + tid] + sP1[7 * 32 + tid];
                const float s  = sB1[jj] + ((s0 + s1) + (s2 + s3));
                const float hv = 0.5f * s * (1.0f + erff(s * 0.70710678118654752f));
                stg_cg(&gH[bb * TDD + jbase + jj], hv);
                __syncwarp();
                if (tid == 0) bar_arrive(&gBarHA[0]);
            }
        }

        // ================= Phase 2: G1B — h rows 4-7 =================
        {
            unsigned long long ax[CJ], ay[CJ];
#pragma unroll
            for (int j = 0; j < CJ; ++j) { ax[j] = 0ull; ay[j] = 0ull; }
#pragma unroll
            for (int j = 0; j < CJ; ++j) {
                const ulonglong2 w0 = *(const ulonglong2*)(sW1 + j * TDD + k1);
                const ulonglong2 w1 = *(const ulonglong2*)(sW1 + j * TDD + k1 + 4);
                fma2(ax[j], w0.x, exB[0].x); fma2(ay[j], w0.y, exB[0].y);
                fma2(ax[j], w1.x, exB[1].x); fma2(ay[j], w1.y, exB[1].y);
            }
            if (t > 0 && tid == 0) bar_spin(&gBarMB[0], (unsigned)t * NCTA);
            __syncthreads();
            const ulonglong2 em0 = ldg128_cg(gMem + (b4 + TBC) * TD + k1);
            const ulonglong2 em1 = ldg128_cg(gMem + (b4 + TBC) * TD + k1 + 4);
#pragma unroll
            for (int j = 0; j < CJ; ++j) {
                const ulonglong2 w0 = *(const ulonglong2*)(sW1 + j * TDD + TD + k1);
                const ulonglong2 w1 = *(const ulonglong2*)(sW1 + j * TDD + TD + k1 + 4);
                fma2(ax[j], w0.x, em0.x); fma2(ay[j], w0.y, em0.y);
                fma2(ax[j], w1.x, em1.x); fma2(ay[j], w1.y, em1.y);
            }
#pragma unroll
            for (int j = 0; j < CJ; ++j) {
                const float2 fx = u2f(ax[j]);
                const float2 fy = u2f(ay[j]);
                float s = (fx.x + fx.y) + (fy.x + fy.y);
                s += __shfl_xor_sync(0xffffffffu, s, 1);
                s += __shfl_xor_sync(0xffffffffu, s, 2);
                s += __shfl_xor_sync(0xffffffffu, s, 4);
                if (kq == 0) sP1[(w << 5) + (b4 << 3) + j] = s;
            }
            __syncthreads();
            if (tid < TBC * CJ) {
                const int bb = tid >> 3, jj = tid & 7;
                const float s0 = sP1[0 * 32 + tid] + sP1[1 * 32 + tid];
                const float s1 = sP1[2 * 32 + tid] + sP1[3 * 32 + tid];
                const float s2 = sP1[4 * 32 + tid] + sP1[5 * 32 + tid];
                const float s3 = sP1[6 * 32 + tid] + sP1[7 * 32 + tid];
                const float s  = sB1[jj] + ((s0 + s1) + (s2 + s3));
                const float hv = 0.5f * s * (1.0f + erff(s * 0.70710678118654752f));
                stg_cg(&gH[(bb + TBC) * TDD + jbase + jj], hv);
                __syncwarp();
                if (tid == 0) bar_arrive(&gBarHB[0]);
            }
        }

        // ================= Phase 3: G2A — mem rows 0-3 =================
        {
            if (tid == 0) bar_spin(&gBarHA[0], (unsigned)(t + 1) * NCTA);
            __syncthreads();
            const float* hr = gH + b4 * TDD + k2;
            const ulonglong2 eh0 = ldg128_cg(hr);
            const ulonglong2 eh1 = ldg128_cg(hr + 4);
            const ulonglong2 eh2 = ldg128_cg(hr + 8);
            const ulonglong2 eh3 = ldg128_cg(hr + 12);
            // prefetch xA(t+1) under eh latency
            {
                const int tn = (t + 1 < TT) ? (t + 1) : t;
                exA[0] = ldg128_nc(x + ((size_t)b4 * TT + tn) * TD + k1);
                exA[1] = ldg128_nc(x + ((size_t)b4 * TT + tn) * TD + k1 + 4);
            }
            unsigned long long px[CI], py[CI];
#pragma unroll
            for (int i = 0; i < CI; ++i) { px[i] = 0ull; py[i] = 0ull; }
#pragma unroll
            for (int i = 0; i < CI; ++i) {
                const float* wr = sW2 + i * TDD + k2;
                const ulonglong2 w0 = *(const ulonglong2*)(wr);
                const ulonglong2 w1 = *(const ulonglong2*)(wr + 4);
                const ulonglong2 w2 = *(const ulonglong2*)(wr + 8);
                const ulonglong2 w3 = *(const ulonglong2*)(wr + 12);
                fma2(px[i], w0.x, eh0.x); fma2(py[i], w0.y, eh0.y);
                fma2(px[i], w1.x, eh1.x); fma2(py[i], w1.y, eh1.y);
                fma2(px[i], w2.x, eh2.x); fma2(py[i], w2.y, eh2.y);
                fma2(px[i], w3.x, eh3.x); fma2(py[i], w3.y, eh3.y);
            }
#pragma unroll
            for (int i = 0; i < CI; ++i) {
                const float2 fx = u2f(px[i]);
                const float2 fy = u2f(py[i]);
                float s = (fx.x + fx.y) + (fy.x + fy.y);
                s += __shfl_xor_sync(0xffffffffu, s, 1);
                s += __shfl_xor_sync(0xffffffffu, s, 2);
                s += __shfl_xor_sync(0xffffffffu, s, 4);
                if (kq == 0) sP2[(w << 4) + (b4 << 2) + i] = s;
            }
            __syncthreads();
            if (tid < 32) {
                if (tid < TBC * CI) {   // 16 threads
                    const int bb = tid >> 2, ii = tid & 3;
                    const float s0 = sP2[0 * 16 + tid] + sP2[1 * 16 + tid];
                    const float s1 = sP2[2 * 16 + tid] + sP2[3 * 16 + tid];
                    const float s2 = sP2[4 * 16 + tid] + sP2[5 * 16 + tid];
                    const float s3 = sP2[6 * 16 + tid] + sP2[7 * 16 + tid];
                    const float p  = sB2[ii] + ((s0 + s1) + (s2 + s3));
                    const float g  = 1.0f / (1.0f + __expf(-p));
                    memA = fmaf(p - memA, g, memA);
                    stg_cg(&gMem[bb * TD + ibase + ii], memA);
                }
                __syncwarp();
                if (tid == 0) bar_arrive(&gBarMA[0]);
                if (tid < TBC * CI)
                    y[((size_t)(tid >> 2) * TT + t) * TD + ibase + (tid & 3)] = memA;
            }
        }

        // ================= Phase 4: G2B — mem rows 4-7 =================
        {
            if (tid == 0) bar_spin(&gBarHB[0], (unsigned)(t + 1) * NCTA);
            __syncthreads();
            const float* hr = gH + (b4 + TBC) * TDD + k2;
            const ulonglong2 eh0 = ldg128_cg(hr);
            const ulonglong2 eh1 = ldg128_cg(hr + 4);
            const ulonglong2 eh2 = ldg128_cg(hr + 8);
            const ulonglong2 eh3 = ldg128_cg(hr + 12);
            // prefetch xB(t+1)
            {
                const int tn = (t + 1 < TT) ? (t + 1) : t;
                exB[0] = ldg128_nc(x + ((size_t)(b4 + TBC) * TT + tn) * TD + k1);
                exB[1] = ldg128_nc(x + ((size_t)(b4 + TBC) * TT + tn) * TD + k1 + 4);
            }
            unsigned long long px[CI], py[CI];
#pragma unroll
            for (int i = 0; i < CI; ++i) { px[i] = 0ull; py[i] = 0ull; }
#pragma unroll
            for (int i = 0; i < CI; ++i) {
                const float* wr = sW2 + i * TDD + k2;
                const ulonglong2 w0 = *(const ulonglong2*)(wr);
                const ulonglong2 w1 = *(const ulonglong2*)(wr + 4);
                const ulonglong2 w2 = *(const ulonglong2*)(wr + 8);
                const ulonglong2 w3 = *(const ulonglong2*)(wr + 12);
                fma2(px[i], w0.x, eh0.x); fma2(py[i], w0.y, eh0.y);
                fma2(px[i], w1.x, eh1.x); fma2(py[i], w1.y, eh1.y);
                fma2(px[i], w2.x, eh2.x); fma2(py[i], w2.y, eh2.y);
                fma2(px[i], w3.x, eh3.x); fma2(py[i], w3.y, eh3.y);
            }
#pragma unroll
            for (int i = 0; i < CI; ++i) {
                const float2 fx = u2f(px[i]);
                const float2 fy = u2f(py[i]);
                float s = (fx.x + fx.y) + (fy.x + fy.y);
                s += __shfl_xor_sync(0xffffffffu, s, 1);
                s += __shfl_xor_sync(0xffffffffu, s, 2);
                s += __shfl_xor_sync(0xffffffffu, s, 4);
                if (kq == 0) sP2[(w << 4) + (b4 << 2) + i] = s;
            }
            __syncthreads();
            if (tid < 32) {
                if (tid < TBC * CI) {
                    const int bb = tid >> 2, ii = tid & 3;
                    const float s0 = sP2[0 * 16 + tid] + sP2[1 * 16 + tid];
                    const float s1 = sP2[2 * 16 + tid] + sP2[3 * 16 + tid];
                    const float s2 = sP2[4 * 16 + tid] + sP2[5 * 16 + tid];
                    const float s3 = sP2[6 * 16 + tid] + sP2[7 * 16 + tid];
                    const float p  = sB2[ii] + ((s0 + s1) + (s2 + s3));
                    const float g  = 1.0f / (1.0f + __expf(-p));
                    memB = fmaf(p - memB, g, memB);
                    stg_cg(&gMem[(bb + TBC) * TD + ibase + ii], memB);
                }
                __syncwarp();
                if (tid == 0) bar_arrive(&gBarMB[0]);
                if (tid < TBC * CI)
                    y[((size_t)((tid >> 2) + TBC) * TT + t) * TD + ibase + (tid & 3)] = memB;
            }
        }
    }
}

extern "C" void kernel_launch(void* const* d_in, const int* in_sizes, int n_in,
                              void* d_out, int out_size) {
    const float* x  = (const float*)d_in[0];
    const float* W1 = (const float*)d_in[1];
    const float* b1 = (const float*)d_in[2];
    const float* W2 = (const float*)d_in[3];
    const float* b2 = (const float*)d_in[4];
    float* y = (float*)d_out;

    const size_t SMEM_BYTES =
        (CJ * TDD + CI * TDD + NWARP * 32 + NWARP * 16 + CJ + CI) * sizeof(float);
    cudaFuncSetAttribute(sys2_kernel,
                         cudaFuncAttributeMaxDynamicSharedMemorySize,
                         (int)SMEM_BYTES);

    init_scratch<<<(TB * TD + 255) / 256, 256>>>();
    sys2_kernel<<<NCTA, NTHR, SMEM_BYTES>>>(x, W1, b1, W2, b2, y);
}

// round 17
// speedup vs baseline: 1.7308x; 1.7308x over previous
#include <cuda_runtime.h>
#include <math.h>

#define TB    8
#define TD    512
#define TDD   1024
#define TT    4096
#define NCTA  128
#define CJ    8        // h cols per CTA
#define NTHR  256
#define NWARP 8
#define MPAD  516      // padded mem row (floats) to stagger SMEM banks

// p accumulators (atomic, parity double-buffered) + barrier counter
__device__ float gP[2][TB * TD];                 // 32 KB
__device__ float gXp[(size_t)TT * NCTA * 64];    // x @ W1x^T, [t][cta][bb*8+jj]
__device__ __align__(256) unsigned gBar[64];

__global__ void init_scratch() {
    int i = blockIdx.x * blockDim.x + threadIdx.x;
    if (i < TB * TD) { gP[0][i] = 0.0f; gP[1][i] = 0.0f; }
    if (i < 64) gBar[i] = 0u;
}

__device__ __forceinline__ void fma2(unsigned long long& acc,
                                     unsigned long long a,
                                     unsigned long long b) {
    asm volatile("fma.rn.f32x2 %0, %1, %2, %0;" : "+l"(acc) : "l"(a), "l"(b));
}
__device__ __forceinline__ float2 u2f(unsigned long long v) {
    float2 f;
    asm("mov.b64 {%0,%1}, %2;" : "=f"(f.x), "=f"(f.y) : "l"(v));
    return f;
}
__device__ __forceinline__ unsigned long long fdup(float v) {
    unsigned long long r;
    asm("mov.b64 %0, {%1,%1};" : "=l"(r) : "f"(v));
    return r;
}
__device__ __forceinline__ float4 ldg128cg4(const float* p) {
    float4 v;
    asm volatile("ld.global.cg.v4.f32 {%0,%1,%2,%3}, [%4];"
                 : "=f"(v.x), "=f"(v.y), "=f"(v.z), "=f"(v.w) : "l"(p));
    return v;
}
__device__ __forceinline__ void redg_add(float* p, float v) {
    asm volatile("red.global.add.f32 [%0], %1;" :: "l"(p), "f"(v) : "memory");
}
__device__ __forceinline__ void bar_arrive(unsigned* ctr) {
    unsigned one = 1u;
    asm volatile("red.release.gpu.global.add.u32 [%0], %1;"
                 :: "l"(ctr), "r"(one) : "memory");
}
__device__ __forceinline__ void bar_spin(const unsigned* ctr, unsigned tgt) {
    unsigned v;
    do {
        asm volatile("ld.relaxed.gpu.global.u32 %0, [%1];"
                     : "=r"(v) : "l"(ctr) : "memory");
    } while (v < tgt);
}

// FMA/ALU-only sigmoid (no MUFU): exp2 bit-trick + Newton reciprocal. ~1e-7 rel.
__device__ __forceinline__ float sigmoid_fast(float p) {
    float z = -p * 1.44269504088896341f;
    z = fminf(fmaxf(z, -126.0f), 126.0f);
    const float MAGIC = 12582912.0f;      // 1.5 * 2^23
    float m = z + MAGIC;
    float nf = m - MAGIC;
    float f = z - nf;
    // 2^f on [-0.5, 0.5], degree-5 minimax
    float ex = 1.8775767e-3f;
    ex = fmaf(ex, f, 8.9893397e-3f);
    ex = fmaf(ex, f, 5.5826318e-2f);
    ex = fmaf(ex, f, 2.4015361e-1f);
    ex = fmaf(ex, f, 6.9315308e-1f);
    ex = fmaf(ex, f, 1.0f);
    int ei = __float_as_int(ex) + (__float_as_int(m) << 23);
    float e = __int_as_float(ei);         // exp(-p)
    float den = 1.0f + e;
    float r = __int_as_float(0x7EF311C3 - __float_as_int(den));
    r = r * (2.0f - den * r);
    r = r * (2.0f - den * r);
    r = r * (2.0f - den * r);
    return r;                              // 1/(1+exp(-p))
}

// ======================= xproj precompute GEMM (validated R9) ==============
#define PM 128
#define PN 64
#define PK 32

__global__ void __launch_bounds__(256, 3)
xproj_kernel(const float* __restrict__ x, const float* __restrict__ W1) {
    __shared__ float As[PK][PM];
    __shared__ unsigned long long Bs[PK][PN];
    const int tid = threadIdx.x;
    const int n0 = blockIdx.x * PN;
    const int m0 = blockIdx.y * PM;
    const int tx = tid & 15;
    const int ty = tid >> 4;

    unsigned long long acc[4][4];
#pragma unroll
    for (int a = 0; a < 4; ++a)
#pragma unroll
        for (int c = 0; c < 4; ++c) acc[a][c] = 0ull;

    for (int kt = 0; kt < 512; kt += PK) {
        __syncthreads();
        {
            const int mm = tid & 127, kh = tid >> 7;
            const float* src = x + (size_t)(m0 + mm) * 512 + kt + kh * 16;
#pragma unroll
            for (int qq = 0; qq < 4; ++qq) {
                float4 v = *(const float4*)(src + qq * 4);
                const int kk = kh * 16 + qq * 4;
                As[kk + 0][mm] = v.x; As[kk + 1][mm] = v.y;
                As[kk + 2][mm] = v.z; As[kk + 3][mm] = v.w;
            }
        }
        {
            const int nn = tid & 63, kh = tid >> 6;
            const float* src = W1 + (size_t)(n0 + nn) * 1024 + kt + kh * 8;
#pragma unroll
            for (int qq = 0; qq < 2; ++qq) {
                float4 v = *(const float4*)(src + qq * 4);
                const int kk = kh * 8 + qq * 4;
                Bs[kk + 0][nn] = fdup(v.x); Bs[kk + 1][nn] = fdup(v.y);
                Bs[kk + 2][nn] = fdup(v.z); Bs[kk + 3][nn] = fdup(v.w);
            }
        }
        __syncthreads();
#pragma unroll
        for (int k = 0; k < PK; ++k) {
            const ulonglong2 a01 = *(const ulonglong2*)&As[k][ty * 8];
            const ulonglong2 a23 = *(const ulonglong2*)&As[k][ty * 8 + 4];
            const ulonglong2 b01 = *(const ulonglong2*)&Bs[k][tx * 4];
            const ulonglong2 b23 = *(const ulonglong2*)&Bs[k][tx * 4 + 2];
            fma2(acc[0][0], a01.x, b01.x); fma2(acc[0][1], a01.x, b01.y);
            fma2(acc[0][2], a01.x, b23.x); fma2(acc[0][3], a01.x, b23.y);
            fma2(acc[1][0], a01.y, b01.x); fma2(acc[1][1], a01.y, b01.y);
            fma2(acc[1][2], a01.y, b23.x); fma2(acc[1][3], a01.y, b23.y);
            fma2(acc[2][0], a23.x, b01.x); fma2(acc[2][1], a23.x, b01.y);
            fma2(acc[2][2], a23.x, b23.x); fma2(acc[2][3], a23.x, b23.y);
            fma2(acc[3][0], a23.y, b01.x); fma2(acc[3][1], a23.y, b01.y);
            fma2(acc[3][2], a23.y, b23.x); fma2(acc[3][3], a23.y, b23.y);
        }
    }
    const int j0 = n0 + tx * 4;
    const size_t jblk = (size_t)(j0 >> 3) * 64 + (j0 & 7);
#pragma unroll
    for (int mp = 0; mp < 4; ++mp) {
        const int m_even = ty * 8 + mp * 2;
#pragma unroll
        for (int par = 0; par < 2; ++par) {
            const int r = m0 + m_even + par;
            const int t = r & 4095, bb = r >> 12;
            float4 v;
            v.x = par ? u2f(acc[mp][0]).y : u2f(acc[mp][0]).x;
            v.y = par ? u2f(acc[mp][1]).y : u2f(acc[mp][1]).x;
            v.z = par ? u2f(acc[mp][2]).y : u2f(acc[mp][2]).x;
            v.w = par ? u2f(acc[mp][3]).y : u2f(acc[mp][3]).x;
            *(float4*)(gXp + (size_t)t * (NCTA * 64) + jblk + bb * 8) = v;
        }
    }
}

// ======================= single-barrier recurrence kernel ==================
__global__ void __launch_bounds__(NTHR, 1)
sys2_kernel(const float* __restrict__ W1,
            const float* __restrict__ b1,
            const float* __restrict__ W2,
            const float* __restrict__ b2,
            float* __restrict__ y)
{
    extern __shared__ float smem[];
    float* sW1m = smem;                      // CJ*512  (16 KB) W1 mem-half slice
    float* sW2T = sW1m + CJ * TD;            // 512*8   (16 KB) W2 column slice
    float* sMem = sW2T + TD * CJ;            // 8*MPAD  (16.5 KB) local full mem
    float* sH   = sMem + TB * MPAD;          // 64: h slice [j][b]
    float* sPart = sH + 64;                  // NWARP*64
    float* sB1  = sPart + NWARP * 64;        // CJ
    float* sB2f = sB1 + CJ;                  // 512 full b2

    const int cta  = blockIdx.x;
    const int tid  = threadIdx.x;
    const int w    = tid >> 5;
    const int lane = tid & 31;
    const int b    = lane >> 2;
    const int kq   = lane & 3;
    const int jbase = cta * CJ;
    const int bq    = tid >> 5;              // mem-update batch row
    const int iBase = (lane) * 16 - (kq * 0); // placeholder; real below
    const int iB    = (tid & 31) * 16;       // mem-update i block
    const bool isNeg = ((tid & 31) == (cta >> 2));   // 8 threads own negation/y
    const int negSel = cta & 3;              // which float4 of the block

    {   // stage weights
        float4* s1 = (float4*)sW1m;
        for (int idx = tid; idx < CJ * TD / 4; idx += NTHR) {
            const int j = idx >> 7, kf = idx & 127;
            s1[idx] = *(const float4*)(W1 + (size_t)(jbase + j) * TDD + TD + kf * 4);
        }
        for (int idx = tid; idx < TD * CJ; idx += NTHR) {
            const int i = idx >> 3, jj = idx & 7;
            sW2T[idx] = W2[(size_t)i * TDD + jbase + jj];
        }
        for (int idx = tid; idx < TB * MPAD; idx += NTHR) sMem[idx] = 0.0f;
        if (tid < CJ) sB1[tid] = b1[jbase + tid];
        for (int idx = tid; idx < TD; idx += NTHR) sB2f[idx] = b2[idx];
    }
    __syncthreads();

    float xq = 0.0f;
    if (tid < TB * CJ)
        xq = __ldg(&gXp[(size_t)0 * (NCTA * 64) + cta * 64 + tid]);

    float4 qNeg = make_float4(0.f, 0.f, 0.f, 0.f);   // raw totals to negate next step

    for (int t = 0; t < TT; ++t) {
        // ---- barrier: p(t-1) complete ----
        if (t > 0 && tid == 0) bar_spin(&gBar[0], (unsigned)t * NCTA);
        __syncthreads();

        float* aBuf = gP[t & 1];                 // this step's add target
        const float* rBuf = gP[(t & 1) ^ 1];     // p(t-1)

        // negation of p(t-2) totals (same buffer as aBuf; adds commute)
        if (t > 0 && isNeg) {
            float* np = aBuf + bq * TD + 4 * cta;
            redg_add(np + 0, -qNeg.x);
            redg_add(np + 1, -qNeg.y);
            redg_add(np + 2, -qNeg.z);
            redg_add(np + 3, -qNeg.w);
        }

        // ---- read p(t-1), local full mem update ----
        const float* rp = rBuf + bq * TD + iB;
        float4 q0 = ldg128cg4(rp);
        float4 q1 = ldg128cg4(rp + 4);
        float4 q2 = ldg128cg4(rp + 8);
        float4 q3 = ldg128cg4(rp + 12);

        float* mp = sMem + bq * MPAD + iB;
        float4 m0 = *(float4*)(mp);
        float4 m1 = *(float4*)(mp + 4);
        float4 m2 = *(float4*)(mp + 8);
        float4 m3 = *(float4*)(mp + 12);
        const float* bp2 = sB2f + iB;

#define UPD(mc, qc, off) do {                                     \
        float pv, gv;                                             \
        pv = qc.x + bp2[off + 0]; gv = sigmoid_fast(pv); mc.x = fmaf(pv - mc.x, gv, mc.x); \
        pv = qc.y + bp2[off + 1]; gv = sigmoid_fast(pv); mc.y = fmaf(pv - mc.y, gv, mc.y); \
        pv = qc.z + bp2[off + 2]; gv = sigmoid_fast(pv); mc.z = fmaf(pv - mc.z, gv, mc.z); \
        pv = qc.w + bp2[off + 3]; gv = sigmoid_fast(pv); mc.w = fmaf(pv - mc.w, gv, mc.w); \
    } while (0)
        UPD(m0, q0, 0); UPD(m1, q1, 4); UPD(m2, q2, 8); UPD(m3, q3, 12);
#undef UPD
        *(float4*)(mp)      = m0;
        *(float4*)(mp + 4)  = m1;
        *(float4*)(mp + 8)  = m2;
        *(float4*)(mp + 12) = m3;

        if (isNeg) {
            // save raw accumulator totals for negation next step; write y(t-1)
            float4 qs, ms;
            switch (negSel) {
                case 0: qs = q0; ms = m0; break;
                case 1: qs = q1; ms = m1; break;
                case 2: qs = q2; ms = m2; break;
                default: qs = q3; ms = m3; break;
            }
            qNeg = qs;
            if (t > 0) {
                float* yp = y + ((size_t)bq * TT + (t - 1)) * TD + 4 * cta;
                yp[0] = ms.x; yp[1] = ms.y; yp[2] = ms.z; yp[3] = ms.w;
            }
        }
        __syncthreads();                      // sMem = mem(t-1) ready

        // ---- GEMM1 (mem-half) from SMEM + xq: h slice ----
        unsigned long long ax[CJ], ay[CJ];
#pragma unroll
        for (int j = 0; j < CJ; ++j) { ax[j] = 0ull; ay[j] = 0ull; }
#pragma unroll
        for (int it = 0; it < 4; ++it) {
            const int k = (w << 6) + (it << 4) + (kq << 2);
            const ulonglong2 em = *(const ulonglong2*)(sMem + b * MPAD + k);
#pragma unroll
            for (int j = 0; j < CJ; ++j) {
                const ulonglong2 wv = *(const ulonglong2*)(sW1m + j * TD + k);
                fma2(ax[j], wv.x, em.x);
                fma2(ay[j], wv.y, em.y);
            }
        }
#pragma unroll
        for (int j = 0; j < CJ; ++j) {
            const float2 fx = u2f(ax[j]);
            const float2 fy = u2f(ay[j]);
            float s = (fx.x + fx.y) + (fy.x + fy.y);
            s += __shfl_xor_sync(0xffffffffu, s, 1);
            s += __shfl_xor_sync(0xffffffffu, s, 2);
            if (kq == 0) sPart[(w << 6) + (b << 3) + j] = s;
        }
        __syncthreads();

        // h epilogue: gelu, store to SMEM [j][b]
        if (tid < TB * CJ) {
            const int bb = tid >> 3, jj = tid & 7;
            const float s0 = sPart[0 * 64 + tid] + sPart[1 * 64 + tid];
            const float s1 = sPart[2 * 64 + tid] + sPart[3 * 64 + tid];
            const float s2 = sPart[4 * 64 + tid] + sPart[5 * 64 + tid];
            const float s3 = sPart[6 * 64 + tid] + sPart[7 * 64 + tid];
            const float s  = sB1[jj] + xq + ((s0 + s1) + (s2 + s3));
            sH[jj * 8 + bb] = 0.5f * s * (1.0f + erff(s * 0.70710678118654752f));
        }
        __syncthreads();

        // ---- outer product: this slice's contribution to all p[b][i] ----
        {
            const int i1 = tid, i2 = tid + 256;
            float w2a[8], w2b[8];
            *(float4*)&w2a[0] = *(const float4*)(sW2T + i1 * 8);
            *(float4*)&w2a[4] = *(const float4*)(sW2T + i1 * 8 + 4);
            *(float4*)&w2b[0] = *(const float4*)(sW2T + i2 * 8);
            *(float4*)&w2b[4] = *(const float4*)(sW2T + i2 * 8 + 4);
            unsigned long long a1[4], a2[4];
#pragma unroll
            for (int bp = 0; bp < 4; ++bp) { a1[bp] = 0ull; a2[bp] = 0ull; }
#pragma unroll
            for (int j = 0; j < 8; ++j) {
                const unsigned long long da = fdup(w2a[j]);
                const unsigned long long db = fdup(w2b[j]);
#pragma unroll
                for (int bp = 0; bp < 4; ++bp) {
                    const unsigned long long hp =
                        *(const unsigned long long*)(sH + j * 8 + 2 * bp);
                    fma2(a1[bp], da, hp);
                    fma2(a2[bp], db, hp);
                }
            }
#pragma unroll
            for (int bp = 0; bp < 4; ++bp) {
                const float2 f1 = u2f(a1[bp]);
                const float2 f2 = u2f(a2[bp]);
                redg_add(aBuf + (2 * bp + 0) * TD + i1, f1.x);
                redg_add(aBuf + (2 * bp + 1) * TD + i1, f1.y);
                redg_add(aBuf + (2 * bp + 0) * TD + i2, f2.x);
                redg_add(aBuf + (2 * bp + 1) * TD + i2, f2.y);
            }
        }
        __syncthreads();                      // all REDGs issued CTA-wide
        if (tid == 0) bar_arrive(&gBar[0]);   // release publishes them

        // prefetch xq(t+1) — overlaps the next barrier wait
        if (tid < TB * CJ) {
            const int tn = (t + 1 < TT) ? (t + 1) : t;
            xq = __ldg(&gXp[(size_t)tn * (NCTA * 64) + cta * 64 + tid]);
        }
    }

    // ---- final: consume p(4095) -> y[4095] ----
    if (tid == 0) bar_spin(&gBar[0], (unsigned)TT * NCTA);
    __syncthreads();
    if (isNeg) {
        const float* rp = gP[(TT & 1) ^ 1] + bq * TD + 4 * cta;
        const float* mp = sMem + bq * MPAD + 4 * cta;
        float* yp = y + ((size_t)bq * TT + (TT - 1)) * TD + 4 * cta;
#pragma unroll
        for (int r = 0; r < 4; ++r) {
            const float pv = rp[r] + sB2f[4 * cta + r];
            const float gv = sigmoid_fast(pv);
            yp[r] = fmaf(pv - mp[r], gv, mp[r]);
        }
    }
    (void)iBase;
}

extern "C" void kernel_launch(void* const* d_in, const int* in_sizes, int n_in,
                              void* d_out, int out_size) {
    const float* x  = (const float*)d_in[0];
    const float* W1 = (const float*)d_in[1];
    const float* b1 = (const float*)d_in[2];
    const float* W2 = (const float*)d_in[3];
    const float* b2 = (const float*)d_in[4];
    float* y = (float*)d_out;

    const size_t SMEM_BYTES =
        (CJ * TD + TD * CJ + TB * MPAD + 64 + NWARP * 64 + CJ + TD) * sizeof(float);
    cudaFuncSetAttribute(sys2_kernel,
                         cudaFuncAttributeMaxDynamicSharedMemorySize,
                         (int)SMEM_BYTES);

    init_scratch<<<(TB * TD + 255) / 256, 256>>>();
    xproj_kernel<<<dim3(TDD / PN, (TB * TT) / PM), 256>>>(x, W1);
    sys2_kernel<<<NCTA, NTHR, SMEM_BYTES>>>(W1, b1, W2, b2, y);
}